// round 16
// baseline (speedup 1.0000x reference)
#include <cuda_runtime.h>
#include <cuda_bf16.h>
#include <cstdint>

// Problem constants
#define BATCH 32
#define CIN   256
#define COUT  256
#define Hh    56
#define Ww    56
#define NPIX  (Hh*Ww)          // 3136
#define CW    8                // 256 bits = 8 x uint32 words per pixel
#define NVALS 100352.0         // BATCH*NPIX per-channel count
#define BN_EPS 1e-5

// ----------------- scratch (device globals; no allocation) -----------------
__device__ unsigned           g_xbits[BATCH * NPIX * CW];       // [b][p][wd]  3.2 MB
__device__ unsigned           g_wbits[COUT * 9 * CW];           // [co][tap][wd]
__device__ float              g_alpha[COUT];
__device__ int                g_sum[COUT];
__device__ unsigned long long g_sumsq[COUT];
__device__ float              g_scale[COUT];
__device__ float              g_shift[COUT];
__device__ int                g_one;                            // runtime 1 (opaque to ptxas)
__device__ short              g_S[BATCH * NPIX * COUT];         // [b][p][co] 51.4 MB

// carry-save adder: 2 LOP3 (0x96 xor3, 0xE8 maj3)
__device__ __forceinline__ void csa(unsigned a, unsigned b, unsigned c,
                                    unsigned& s, unsigned& cy) {
    s  = a ^ b ^ c;
    cy = (a & b) | (a & c) | (b & c);
}

// forced IMAD accumulate: acc += v * k  (k is a runtime reg ptxas can't fold,
// so this stays an IMAD on the fma pipe instead of an IADD3 on the alu pipe)
#define MADACC(acc, v, k) \
    asm("mad.lo.s32 %0, %1, %2, %0;" : "+r"(acc) : "r"((int)(v)), "r"(k))

// ----------------- kernel 1: zero the stats accumulators -----------------
__global__ void zero_stats_kernel() {
    int t = threadIdx.x;
    if (t < COUT) { g_sum[t] = 0; g_sumsq[t] = 0ull; }
    if (t == 0) g_one = 1;
}

// ----------------- kernel 2: weight prep -----------------
__global__ void __launch_bounds__(256) prep_w_kernel(const float* __restrict__ w) {
    int co   = blockIdx.x;
    int ci   = threadIdx.x;           // 0..255
    int lane = ci & 31;
    int warp = ci >> 5;               // = word index (ci/32)

    float v[9];
    const float* wp = w + ((size_t)co * CIN + ci) * 9;
#pragma unroll
    for (int t = 0; t < 9; t++) v[t] = wp[t];

    __shared__ float part[8][9];
    __shared__ float tapmean[9];

#pragma unroll
    for (int t = 0; t < 9; t++) {
        float s = v[t];
#pragma unroll
        for (int o = 16; o > 0; o >>= 1) s += __shfl_down_sync(0xffffffffu, s, o);
        if (lane == 0) part[warp][t] = s;
    }
    __syncthreads();
    if (ci < 9) {
        float s = 0.f;
#pragma unroll
        for (int i = 0; i < 8; i++) s += part[i][ci];
        tapmean[ci] = s * (1.0f / 256.0f);
    }
    __syncthreads();

    float asum = 0.f;
#pragma unroll
    for (int t = 0; t < 9; t++) {
        float wc = v[t] - tapmean[t];
        wc = fminf(fmaxf(wc, -1.0f), 1.0f);
        asum += fabsf(wc);
        unsigned m = __ballot_sync(0xffffffffu, wc < 0.0f);
        if (lane == 0) g_wbits[co * 72 + t * CW + warp] = m;
    }
    __syncthreads();
#pragma unroll
    for (int o = 16; o > 0; o >>= 1) asum += __shfl_down_sync(0xffffffffu, asum, o);
    if (lane == 0) part[warp][0] = asum;
    __syncthreads();
    if (ci == 0) {
        float tot = 0.f;
#pragma unroll
        for (int i = 0; i < 8; i++) tot += part[i][0];
        g_alpha[co] = tot * (1.0f / 2304.0f);
    }
}

// ----------------- kernel 3: binarize x into bit-planes (float4, 4 pixels/thread) -----------------
__global__ void __launch_bounds__(256) binarize_kernel(const float* __restrict__ x) {
    int idx = blockIdx.x * 256 + threadIdx.x;       // 0 .. BATCH*CW*(NPIX/4)-1
    if (idx >= BATCH * CW * (NPIX / 4)) return;
    int p4 = idx % (NPIX / 4);
    int wd = (idx / (NPIX / 4)) % CW;
    int b  = idx / ((NPIX / 4) * CW);

    const float* xp = x + ((size_t)(b * CIN + wd * 32) * NPIX) + p4 * 4;
    unsigned m0 = 0u, m1 = 0u, m2 = 0u, m3 = 0u;
#pragma unroll
    for (int k = 0; k < 32; k++) {
        float4 v = *(const float4*)(xp + (size_t)k * NPIX);
        m0 |= (v.x < 0.0f ? 1u : 0u) << k;
        m1 |= (v.y < 0.0f ? 1u : 0u) << k;
        m2 |= (v.z < 0.0f ? 1u : 0u) << k;
        m3 |= (v.w < 0.0f ? 1u : 0u) << k;
    }
    size_t base = ((size_t)(b * NPIX + p4 * 4)) * CW + wd;
    g_xbits[base]          = m0;
    g_xbits[base + CW]     = m1;
    g_xbits[base + 2 * CW] = m2;
    g_xbits[base + 3 * CW] = m3;
}

// ----------------- kernel 4: XNOR conv, dual-row blocks, L0-CSA + POPC -----------------
// Block = (hb, b): h-rows 2*hb and 2*hb+1. 512 threads; pair (2i,2i+1) = cout i,
// ci halves [0,128)/[128,256). Two interleaved CSA trees (one per row) share
// x-row loads. L0 CSA only; popc pools directly: P = p1 + 2*p2 (exact).
// popc accumulation is forced onto the fma pipe via MADACC (IMAD with runtime k=1).
__global__ void __launch_bounds__(512) conv_kernel() {
    int hb  = blockIdx.x;      // 0..27
    int b   = blockIdx.y;      // 0..31
    int h0  = hb * 2;          // row A
    int h1  = h0 + 1;          // row B
    int tid = threadIdx.x;     // 0..511
    int co   = tid >> 1;       // 0..255
    int half = tid & 1;        // 0 = words 0-3, 1 = words 4-7

    const int kone = g_one;    // runtime 1; keeps MADACC as IMAD

    __shared__ unsigned sx[4][Ww + 2][CW];    // tile rows h0-1 .. h0+2, padded cols

    for (int i = tid; i < 4 * (Ww + 2) * CW; i += 512) ((unsigned*)sx)[i] = 0u;
    __syncthreads();
#pragma unroll
    for (int r = 0; r < 4; r++) {
        int gh = h0 - 1 + r;
        if (gh >= 0 && gh < Hh) {
            const unsigned* src = g_xbits + ((size_t)(b * NPIX + gh * Ww)) * CW;
            unsigned* dst = &sx[r][1][0];
            for (int i = tid; i < Ww * CW; i += 512) dst[i] = src[i];
        }
    }
    __syncthreads();

    // per-thread weights: 9 taps x 4 words (this half)
    unsigned wreg[36];
    {
        const unsigned* wp = g_wbits + co * 72 + half * 4;
#pragma unroll
        for (int t = 0; t < 9; t++) {
            uint4 q = *(const uint4*)(wp + t * CW);
            wreg[t * 4 + 0] = q.x; wreg[t * 4 + 1] = q.y;
            wreg[t * 4 + 2] = q.z; wreg[t * 4 + 3] = q.w;
        }
    }
    // per-tap weight popcounts (this half) for border corrections
    int nw[9];
#pragma unroll
    for (int t = 0; t < 9; t++)
        nw[t] = __popc(wreg[t*4]) + __popc(wreg[t*4+1]) + __popc(wreg[t*4+2]) + __popc(wreg[t*4+3]);

    int nwc0 = nw[0] + nw[3] + nw[6];
    int nwc2 = nw[2] + nw[5] + nw[8];

    // row A (h0): only possible invalid row is tap-row 0 (h0==0)
    int rflagA = (h0 == 0) ? 1 : 0;
    int nvA    = rflagA ? 6 : 9;
    int corrA  = rflagA ? (nw[0] + nw[1] + nw[2]) : 0;
    int cornA  = rflagA ? nw[0] : 0;     // corner tap for w=0
    int cornA2 = rflagA ? nw[2] : 0;     // corner tap for w=55
    // row B (h1): only possible invalid row is tap-row 2 (h1==55)
    int rflagB = (h1 == Hh - 1) ? 1 : 0;
    int nvB    = rflagB ? 6 : 9;
    int corrB  = rflagB ? (nw[6] + nw[7] + nw[8]) : 0;
    int cornB  = rflagB ? nw[6] : 0;     // corner tap for w=0
    int cornB2 = rflagB ? nw[8] : 0;     // corner tap for w=55

    short* soutA = g_S + ((size_t)(b * NPIX) + h0 * Ww) * COUT + co;
    short* soutB = g_S + ((size_t)(b * NPIX) + h1 * Ww) * COUT + co;
    int lsum = 0, lsq = 0;

    // compute P for both rows at window position w (L0 CSA + popc, IMAD accumulation)
    auto computeP2 = [&](int w, int& PA, int& PB) {
        int p1A = 0, p2A = 0, p1B = 0, p2B = 0;
#pragma unroll
        for (int c = 0; c < 3; c++) {
            uint4 x0 = *(const uint4*)(&sx[0][w + c][half * 4]);
            uint4 x1 = *(const uint4*)(&sx[1][w + c][half * 4]);
            uint4 x2 = *(const uint4*)(&sx[2][w + c][half * 4]);
            uint4 x3 = *(const uint4*)(&sx[3][w + c][half * 4]);
            unsigned r0[4] = {x0.x, x0.y, x0.z, x0.w};
            unsigned r1[4] = {x1.x, x1.y, x1.z, x1.w};
            unsigned r2[4] = {x2.x, x2.y, x2.z, x2.w};
            unsigned r3[4] = {x3.x, x3.y, x3.z, x3.w};
#pragma unroll
            for (int j = 0; j < 4; j++) {
                unsigned w0 = wreg[(0 * 3 + c) * 4 + j];
                unsigned w1 = wreg[(1 * 3 + c) * 4 + j];
                unsigned w2 = wreg[(2 * 3 + c) * 4 + j];
                unsigned sA, cA, sB, cB;
                csa(r0[j] ^ w0, r1[j] ^ w1, r2[j] ^ w2, sA, cA);
                csa(r1[j] ^ w0, r2[j] ^ w1, r3[j] ^ w2, sB, cB);
                MADACC(p1A, __popc(sA), kone);
                MADACC(p2A, __popc(cA), kone);
                MADACC(p1B, __popc(sB), kone);
                MADACC(p2B, __popc(cB), kone);
            }
        }
        PA = p1A + 2 * p2A;
        PB = p1B + 2 * p2B;
    };

    auto emit = [&](int w, int nvalA, int corA, int nvalB, int corB) {
        int PA, PB;
        computeP2(w, PA, PB);
        int ShA = 128 * nvalA - 2 * PA + 2 * corA;
        int ShB = 128 * nvalB - 2 * PB + 2 * corB;
        int SA = ShA + __shfl_xor_sync(0xffffffffu, ShA, 1);
        int SB = ShB + __shfl_xor_sync(0xffffffffu, ShB, 1);
        if (half == 0) {
            soutA[(size_t)w * COUT] = (short)SA;
            soutB[(size_t)w * COUT] = (short)SB;
            lsum += SA + SB;
            lsq  += SA * SA + SB * SB;   // <= 112*2304^2 = 5.9e8 < INT_MAX
        }
    };

    // peel borders; border column: nvalid = nv - 3 + rflag (corner overlap)
    emit(0,      nvA - 3 + rflagA, corrA + nwc0 - cornA,
                 nvB - 3 + rflagB, corrB + nwc0 - cornB);
#pragma unroll 3
    for (int w = 1; w < Ww - 1; w++) emit(w, nvA, corrA, nvB, corrB);
    emit(Ww - 1, nvA - 3 + rflagA, corrA + nwc2 - cornA2,
                 nvB - 3 + rflagB, corrB + nwc2 - cornB2);

    if (half == 0) {
        atomicAdd(&g_sum[co], lsum);
        atomicAdd(&g_sumsq[co], (unsigned long long)(long long)lsq);
    }
}

// ----------------- kernel 5: finalize per-channel thresholds -----------------
__global__ void finalize_kernel(const float* __restrict__ gamma,
                                const float* __restrict__ beta) {
    int co = threadIdx.x;
    if (co >= COUT) return;
    double s    = (double)g_sum[co];
    double sq   = (double)(long long)g_sumsq[co];
    double mean = s / NVALS;
    double var  = sq / NVALS - mean * mean;            // exact var of integer S
    double a    = (double)g_alpha[co];
    double inv  = 1.0 / sqrt(a * a * var + BN_EPS);
    double sc   = (double)gamma[co] * a * inv;
    g_scale[co] = (float)sc;
    g_shift[co] = (float)((double)beta[co] - sc * mean);
}

// ----------------- kernel 6: threshold + transpose [b][p][co] -> [b][co][p] -----------------
__global__ void __launch_bounds__(256) thresh_kernel(float* __restrict__ out) {
    __shared__ float tile[32][33];
    int p0  = blockIdx.x * 32;     // 98 tiles (3136 = 98*32)
    int co0 = blockIdx.y * 32;     // 8 tiles
    int b   = blockIdx.z;
    int tx  = threadIdx.x;         // 0..31
    int ty  = threadIdx.y;         // 0..7

    float sc = g_scale[co0 + tx];
    float sh = g_shift[co0 + tx];
#pragma unroll
    for (int r = 0; r < 4; r++) {
        int pl = ty * 4 + r;
        short s = g_S[((size_t)(b * NPIX + p0 + pl)) * COUT + co0 + tx];
        tile[pl][tx] = (fmaf(sc, (float)s, sh) > 0.0f) ? 1.0f : 0.0f;
    }
    __syncthreads();
#pragma unroll
    for (int r = 0; r < 4; r++) {
        int cl = ty * 4 + r;
        out[((size_t)(b * COUT + co0 + cl)) * NPIX + p0 + tx] = tile[tx][cl];
    }
}

// ----------------- launch -----------------
extern "C" void kernel_launch(void* const* d_in, const int* in_sizes, int n_in,
                              void* d_out, int out_size) {
    const float* x      = (const float*)d_in[0];
    const float* weight = (const float*)d_in[1];
    // const float* bias = (const float*)d_in[2];  // cancels inside BN; unused
    const float* gamma  = (const float*)d_in[3];
    const float* beta   = (const float*)d_in[4];
    float* out = (float*)d_out;

    zero_stats_kernel<<<1, 256>>>();
    prep_w_kernel<<<COUT, 256>>>(weight);
    {
        int nthreads = BATCH * CW * (NPIX / 4);
        binarize_kernel<<<(nthreads + 255) / 256, 256>>>(x);
    }
    conv_kernel<<<dim3(Hh / 2, BATCH), 512>>>();
    finalize_kernel<<<1, 256>>>(gamma, beta);
    thresh_kernel<<<dim3(NPIX / 32, COUT / 32, BATCH), dim3(32, 8)>>>(out);
}